// round 1
// baseline (speedup 1.0000x reference)
#include <cuda_runtime.h>

#define D_MODEL 1024
#define N_HEADS 16
#define DK 64
#define BATCH 2
#define MAX_S 4096

// Scratch: __device__ globals (allocation inside kernel_launch is forbidden).
__device__ float g_Q [BATCH * MAX_S * D_MODEL];
__device__ float g_K [BATCH * MAX_S * D_MODEL];
__device__ float g_V [BATCH * MAX_S * D_MODEL];
__device__ float g_AO[BATCH * MAX_S * D_MODEL];

// ---------------------------------------------------------------------------
// C[M,N] = A[M,K] @ W[N,K]^T + bias   (torch F.linear semantics)
// 128x128 tile, BK=16, 256 threads, 8x8 microtile.
// ---------------------------------------------------------------------------
__global__ __launch_bounds__(256, 2)
void gemm_bias_kernel(const float* __restrict__ A, const float* __restrict__ W,
                      const float* __restrict__ bias, float* __restrict__ C,
                      int M, int N, int K)
{
    __shared__ float As[16][128];
    __shared__ float Bs[16][128];

    const int tid = threadIdx.x;
    const int tx = tid & 15;
    const int ty = tid >> 4;
    const int m0 = blockIdx.y * 128;
    const int n0 = blockIdx.x * 128;

    const int lrow = tid >> 2;   // 0..63
    const int lk4  = tid & 3;    // 0..3

    float acc[8][8];
    #pragma unroll
    for (int i = 0; i < 8; i++)
        #pragma unroll
        for (int j = 0; j < 8; j++)
            acc[i][j] = 0.0f;

    for (int k0 = 0; k0 < K; k0 += 16) {
        #pragma unroll
        for (int v = 0; v < 2; v++) {
            int row = lrow + v * 64;
            float4 ta = *(const float4*)(A + (size_t)(m0 + row) * K + k0 + lk4 * 4);
            As[lk4*4+0][row] = ta.x;
            As[lk4*4+1][row] = ta.y;
            As[lk4*4+2][row] = ta.z;
            As[lk4*4+3][row] = ta.w;
            float4 tb = *(const float4*)(W + (size_t)(n0 + row) * K + k0 + lk4 * 4);
            Bs[lk4*4+0][row] = tb.x;
            Bs[lk4*4+1][row] = tb.y;
            Bs[lk4*4+2][row] = tb.z;
            Bs[lk4*4+3][row] = tb.w;
        }
        __syncthreads();

        #pragma unroll
        for (int kk = 0; kk < 16; kk++) {
            float a[8], b[8];
            *(float4*)&a[0] = *(const float4*)&As[kk][ty * 8];
            *(float4*)&a[4] = *(const float4*)&As[kk][ty * 8 + 4];
            *(float4*)&b[0] = *(const float4*)&Bs[kk][tx * 8];
            *(float4*)&b[4] = *(const float4*)&Bs[kk][tx * 8 + 4];
            #pragma unroll
            for (int i = 0; i < 8; i++)
                #pragma unroll
                for (int j = 0; j < 8; j++)
                    acc[i][j] = fmaf(a[i], b[j], acc[i][j]);
        }
        __syncthreads();
    }

    #pragma unroll
    for (int i = 0; i < 8; i++) {
        int m = m0 + ty * 8 + i;
        #pragma unroll
        for (int j4 = 0; j4 < 2; j4++) {
            int n = n0 + tx * 8 + j4 * 4;
            float4 bv = *(const float4*)(bias + n);
            float4 o;
            o.x = acc[i][j4*4+0] + bv.x;
            o.y = acc[i][j4*4+1] + bv.y;
            o.z = acc[i][j4*4+2] + bv.z;
            o.w = acc[i][j4*4+3] + bv.w;
            *(float4*)(C + (size_t)m * N + n) = o;
        }
    }
}

// ---------------------------------------------------------------------------
// Flash attention, fp32. One CTA per (b, h, 128-query block). BKV = 64.
// 256 threads (tx 0..15, ty 0..15); microtile: 8 rows x 4 strided cols (tx+16j).
// Dynamic smem layout:
//   Qs [128][64]   (pre-scaled by 1/sqrt(dk))
//   Kst[64][65]    (transposed: [d][key], padded)
//   Vs [64][64]    ([key][d])
//   Ps [128][64]
// ---------------------------------------------------------------------------
#define FLASH_SMEM_FLOATS (128*64 + 64*65 + 64*64 + 128*64)
#define FLASH_SMEM_BYTES  (FLASH_SMEM_FLOATS * 4)

__global__ __launch_bounds__(256, 2)
void flash_attn_kernel(const float* __restrict__ Q, const float* __restrict__ K,
                       const float* __restrict__ V, float* __restrict__ O, int S)
{
    extern __shared__ float smem[];
    float* Qs  = smem;                 // 128*64
    float* Kst = Qs  + 128 * 64;       // 64*65
    float* Vs  = Kst + 64 * 65;        // 64*64
    float* Ps  = Vs  + 64 * 64;        // 128*64

    const int tid = threadIdx.x;
    const int tx = tid & 15;
    const int ty = tid >> 4;
    const int bh = blockIdx.y;
    const int b = bh >> 4;
    const int h = bh & 15;
    const int q0 = blockIdx.x * 128;

    const float* Qb = Q + ((size_t)(b * S + q0)) * D_MODEL + h * DK;
    const float* Kb = K + ((size_t)b * S) * D_MODEL + h * DK;
    const float* Vb = V + ((size_t)b * S) * D_MODEL + h * DK;

    // Load Q tile, folding in the 1/sqrt(dk) = 0.125 score scale.
    #pragma unroll
    for (int v = 0; v < 8; v++) {
        int idx = tid + v * 256;
        int row = idx >> 4;
        int d4  = idx & 15;
        float4 t = *(const float4*)(Qb + (size_t)row * D_MODEL + d4 * 4);
        t.x *= 0.125f; t.y *= 0.125f; t.z *= 0.125f; t.w *= 0.125f;
        *(float4*)&Qs[row * 64 + d4 * 4] = t;
    }

    float m_i[8], l_i[8], acc[8][4];
    #pragma unroll
    for (int i = 0; i < 8; i++) {
        m_i[i] = -1e30f;
        l_i[i] = 0.0f;
        #pragma unroll
        for (int j = 0; j < 4; j++) acc[i][j] = 0.0f;
    }

    const int nkb = S >> 6;
    for (int kb = 0; kb < nkb; kb++) {
        __syncthreads();   // previous iter done reading Vs/Ps/Kst (and Qs init)

        // Load K (transposed) and V tiles for this key block.
        #pragma unroll
        for (int v = 0; v < 4; v++) {
            int idx = tid + v * 256;
            int key = idx >> 4;
            int d4  = idx & 15;
            const float* kp = Kb + (size_t)(kb * 64 + key) * D_MODEL + d4 * 4;
            float4 t = *(const float4*)kp;
            Kst[(d4*4+0) * 65 + key] = t.x;
            Kst[(d4*4+1) * 65 + key] = t.y;
            Kst[(d4*4+2) * 65 + key] = t.z;
            Kst[(d4*4+3) * 65 + key] = t.w;
            const float* vp = Vb + (size_t)(kb * 64 + key) * D_MODEL + d4 * 4;
            *(float4*)&Vs[key * 64 + d4 * 4] = *(const float4*)vp;
        }
        __syncthreads();

        // S = Qs @ Kst  (rows ty*8+i, cols tx+16j)
        float s[8][4];
        #pragma unroll
        for (int i = 0; i < 8; i++)
            #pragma unroll
            for (int j = 0; j < 4; j++)
                s[i][j] = 0.0f;

        #pragma unroll
        for (int d4 = 0; d4 < 16; d4++) {
            float a[8][4];
            #pragma unroll
            for (int i = 0; i < 8; i++)
                *(float4*)a[i] = *(const float4*)&Qs[(ty*8 + i) * 64 + d4 * 4];
            #pragma unroll
            for (int q = 0; q < 4; q++) {
                float bb[4];
                #pragma unroll
                for (int j = 0; j < 4; j++)
                    bb[j] = Kst[(d4*4 + q) * 65 + tx + 16*j];
                #pragma unroll
                for (int i = 0; i < 8; i++)
                    #pragma unroll
                    for (int j = 0; j < 4; j++)
                        s[i][j] = fmaf(a[i][q], bb[j], s[i][j]);
            }
        }

        // Online softmax (row reductions over the 16 tx lanes of each half-warp).
        #pragma unroll
        for (int i = 0; i < 8; i++) {
            float mx = fmaxf(fmaxf(s[i][0], s[i][1]), fmaxf(s[i][2], s[i][3]));
            #pragma unroll
            for (int off = 8; off >= 1; off >>= 1)
                mx = fmaxf(mx, __shfl_xor_sync(0xffffffffu, mx, off));
            float mnew  = fmaxf(m_i[i], mx);
            float alpha = __expf(m_i[i] - mnew);
            m_i[i] = mnew;
            float rs = 0.0f;
            #pragma unroll
            for (int j = 0; j < 4; j++) {
                s[i][j] = __expf(s[i][j] - mnew);
                rs += s[i][j];
            }
            #pragma unroll
            for (int off = 8; off >= 1; off >>= 1)
                rs += __shfl_xor_sync(0xffffffffu, rs, off);
            l_i[i] = l_i[i] * alpha + rs;
            #pragma unroll
            for (int j = 0; j < 4; j++) {
                acc[i][j] *= alpha;
                Ps[(ty*8 + i) * 64 + tx + 16*j] = s[i][j];
            }
        }
        __syncthreads();

        // O += P @ V
        #pragma unroll
        for (int k4 = 0; k4 < 16; k4++) {
            float a[8][4];
            #pragma unroll
            for (int i = 0; i < 8; i++)
                *(float4*)a[i] = *(const float4*)&Ps[(ty*8 + i) * 64 + k4 * 4];
            #pragma unroll
            for (int q = 0; q < 4; q++) {
                float bb[4];
                #pragma unroll
                for (int j = 0; j < 4; j++)
                    bb[j] = Vs[(k4*4 + q) * 64 + tx + 16*j];
                #pragma unroll
                for (int i = 0; i < 8; i++)
                    #pragma unroll
                    for (int j = 0; j < 4; j++)
                        acc[i][j] = fmaf(a[i][q], bb[j], acc[i][j]);
            }
        }
    }

    // Normalize and store (layout [B*S, D_MODEL], ready for the output GEMM).
    float* Ob = O + ((size_t)(b * S + q0)) * D_MODEL + h * DK;
    #pragma unroll
    for (int i = 0; i < 8; i++) {
        float inv = 1.0f / l_i[i];
        #pragma unroll
        for (int j = 0; j < 4; j++)
            Ob[(size_t)(ty*8 + i) * D_MODEL + tx + 16*j] = acc[i][j] * inv;
    }
}

// ---------------------------------------------------------------------------
extern "C" void kernel_launch(void* const* d_in, const int* in_sizes, int n_in,
                              void* d_out, int out_size)
{
    (void)n_in; (void)out_size;
    const float* query = (const float*)d_in[0];
    const float* key   = (const float*)d_in[1];
    const float* value = (const float*)d_in[2];
    const float* Wq = (const float*)d_in[3];
    const float* bq = (const float*)d_in[4];
    const float* Wk = (const float*)d_in[5];
    const float* bk = (const float*)d_in[6];
    const float* Wv = (const float*)d_in[7];
    const float* bv = (const float*)d_in[8];
    const float* Wo = (const float*)d_in[9];
    const float* bo = (const float*)d_in[10];
    float* out = (float*)d_out;

    const int M = in_sizes[0] / D_MODEL;   // B*S = 8192
    const int S = M / BATCH;               // 4096

    float *pQ, *pK, *pV, *pAO;
    cudaGetSymbolAddress((void**)&pQ,  g_Q);
    cudaGetSymbolAddress((void**)&pK,  g_K);
    cudaGetSymbolAddress((void**)&pV,  g_V);
    cudaGetSymbolAddress((void**)&pAO, g_AO);

    cudaFuncSetAttribute(flash_attn_kernel,
                         cudaFuncAttributeMaxDynamicSharedMemorySize,
                         FLASH_SMEM_BYTES);

    dim3 gblk(D_MODEL / 128, M / 128);   // (8, 64)
    gemm_bias_kernel<<<gblk, 256>>>(query, Wq, bq, pQ, M, D_MODEL, D_MODEL);
    gemm_bias_kernel<<<gblk, 256>>>(key,   Wk, bk, pK, M, D_MODEL, D_MODEL);
    gemm_bias_kernel<<<gblk, 256>>>(value, Wv, bv, pV, M, D_MODEL, D_MODEL);

    flash_attn_kernel<<<dim3(S / 128, BATCH * N_HEADS), 256, FLASH_SMEM_BYTES>>>(
        pQ, pK, pV, pAO, S);

    gemm_bias_kernel<<<gblk, 256>>>(pAO, Wo, bo, out, M, D_MODEL, D_MODEL);
}

// round 4
// speedup vs baseline: 1.8085x; 1.8085x over previous
#include <cuda_runtime.h>
#include <cstdint>

#define D_MODEL 1024
#define N_HEADS 16
#define DK 64
#define BATCH 2
#define MAX_S 4096

// Scratch: __device__ globals (allocation inside kernel_launch is forbidden).
__device__ float g_Q [BATCH * MAX_S * D_MODEL];
__device__ float g_K [BATCH * MAX_S * D_MODEL];
__device__ float g_V [BATCH * MAX_S * D_MODEL];
__device__ float g_AO[BATCH * MAX_S * D_MODEL];

// ---------------------------------------------------------------------------
// Helpers
// ---------------------------------------------------------------------------
__device__ __forceinline__ float ex2f(float x) {
    float y; asm("ex2.approx.ftz.f32 %0, %1;" : "=f"(y) : "f"(x)); return y;
}
__device__ __forceinline__ uint32_t f2tf32(float x) {
    uint32_t r; asm("cvt.rna.tf32.f32 %0, %1;" : "=r"(r) : "f"(x)); return r;
}

// mma.sync m16n8k8 tf32 (sm_80+, portable target): D += A*B, fp32 accum.
#define MMA_TF32(c, a, b0, b1) \
    asm volatile("mma.sync.aligned.m16n8k8.row.col.f32.tf32.tf32.f32 " \
        "{%0,%1,%2,%3}, {%4,%5,%6,%7}, {%8,%9}, {%0,%1,%2,%3};" \
        : "+f"((c)[0]), "+f"((c)[1]), "+f"((c)[2]), "+f"((c)[3]) \
        : "r"((a)[0]), "r"((a)[1]), "r"((a)[2]), "r"((a)[3]), \
          "r"(b0), "r"(b1))

// ---------------------------------------------------------------------------
// GEMM: C[M,N] = A[M,K] @ W[N,K]^T + bias   (Round-1 kernel, known-good)
// ---------------------------------------------------------------------------
__global__ __launch_bounds__(256, 2)
void gemm_bias_kernel(const float* __restrict__ A, const float* __restrict__ W,
                      const float* __restrict__ bias, float* __restrict__ C,
                      int M, int N, int K)
{
    __shared__ float As[16][128];
    __shared__ float Bs[16][128];

    const int tid = threadIdx.x;
    const int tx = tid & 15;
    const int ty = tid >> 4;
    const int m0 = blockIdx.y * 128;
    const int n0 = blockIdx.x * 128;
    const int lrow = tid >> 2;
    const int lk4  = tid & 3;

    float acc[8][8];
    #pragma unroll
    for (int i = 0; i < 8; i++)
        #pragma unroll
        for (int j = 0; j < 8; j++) acc[i][j] = 0.0f;

    for (int k0 = 0; k0 < K; k0 += 16) {
        #pragma unroll
        for (int v = 0; v < 2; v++) {
            int row = lrow + v * 64;
            float4 ta = *(const float4*)(A + (size_t)(m0 + row) * K + k0 + lk4 * 4);
            As[lk4*4+0][row] = ta.x; As[lk4*4+1][row] = ta.y;
            As[lk4*4+2][row] = ta.z; As[lk4*4+3][row] = ta.w;
            float4 tb = *(const float4*)(W + (size_t)(n0 + row) * K + k0 + lk4 * 4);
            Bs[lk4*4+0][row] = tb.x; Bs[lk4*4+1][row] = tb.y;
            Bs[lk4*4+2][row] = tb.z; Bs[lk4*4+3][row] = tb.w;
        }
        __syncthreads();
        #pragma unroll
        for (int kk = 0; kk < 16; kk++) {
            float a[8], b[8];
            *(float4*)&a[0] = *(const float4*)&As[kk][ty * 8];
            *(float4*)&a[4] = *(const float4*)&As[kk][ty * 8 + 4];
            *(float4*)&b[0] = *(const float4*)&Bs[kk][tx * 8];
            *(float4*)&b[4] = *(const float4*)&Bs[kk][tx * 8 + 4];
            #pragma unroll
            for (int i = 0; i < 8; i++)
                #pragma unroll
                for (int j = 0; j < 8; j++)
                    acc[i][j] = fmaf(a[i], b[j], acc[i][j]);
        }
        __syncthreads();
    }

    #pragma unroll
    for (int i = 0; i < 8; i++) {
        int m = m0 + ty * 8 + i;
        #pragma unroll
        for (int j4 = 0; j4 < 2; j4++) {
            int n = n0 + tx * 8 + j4 * 4;
            float4 bv = *(const float4*)(bias + n);
            float4 o;
            o.x = acc[i][j4*4+0] + bv.x; o.y = acc[i][j4*4+1] + bv.y;
            o.z = acc[i][j4*4+2] + bv.z; o.w = acc[i][j4*4+3] + bv.w;
            *(float4*)(C + (size_t)m * N + n) = o;
        }
    }
}

// ---------------------------------------------------------------------------
// Flash attention via mma.sync m16n8k8 tf32.
// CTA = (b, h, 128-q tile). 256 threads = 8 warps; warp w owns q rows
// [w*16, w*16+16). KV blocks of 64. Q fragments register-resident (reused
// across all KV blocks). K,V tiles in smem [64][68] (pad-68 => conflict-free
// fragment loads). Softmax is quad-local; P->A fragments via shuffles.
//
// Fragment maps (m16n8k8, lane: gr = lane>>2, tig = lane&3):
//   A(16x8 row):  a0=(gr,tig) a1=(gr+8,tig) a2=(gr,tig+4) a3=(gr+8,tig+4)
//   B(8x8 col):   b0=(k=tig, n=gr)  b1=(k=tig+4, n=gr)
//   C(16x8):      c0=(gr,2tig) c1=(gr,2tig+1) c2=(gr+8,2tig) c3=(gr+8,2tig+1)
// ---------------------------------------------------------------------------
__global__ __launch_bounds__(256, 2)
void flash_mma_kernel(const float* __restrict__ Q, const float* __restrict__ K,
                      const float* __restrict__ V, float* __restrict__ O, int S)
{
    __shared__ uint32_t Kt[64 * 68];
    __shared__ uint32_t Vs[64 * 68];

    const int tid  = threadIdx.x;
    const int wid  = tid >> 5;
    const int lane = tid & 31;
    const int gr   = lane >> 2;
    const int tig  = lane & 3;

    const int q0 = blockIdx.x * 128;
    const int b  = blockIdx.y >> 4;
    const int h  = blockIdx.y & 15;
    const int m0 = wid * 16;             // warp's q-row base within tile

    const float* Qb = Q + ((size_t)b * S + q0) * D_MODEL + h * DK;
    const float* Kb = K + (size_t)b * S * D_MODEL + h * DK;
    const float* Vb = V + (size_t)b * S * D_MODEL + h * DK;

    // Q fragments: fold in 1/sqrt(dk) * log2(e) so softmax uses ex2.
    const float QSCALE = 0.125f * 1.4426950408889634f;
    uint32_t qf[8][4];
    #pragma unroll
    for (int kk = 0; kk < 8; kk++) {
        qf[kk][0] = f2tf32(Qb[(size_t)(m0 + gr)     * D_MODEL + kk*8 + tig]     * QSCALE);
        qf[kk][1] = f2tf32(Qb[(size_t)(m0 + gr + 8) * D_MODEL + kk*8 + tig]     * QSCALE);
        qf[kk][2] = f2tf32(Qb[(size_t)(m0 + gr)     * D_MODEL + kk*8 + tig + 4] * QSCALE);
        qf[kk][3] = f2tf32(Qb[(size_t)(m0 + gr + 8) * D_MODEL + kk*8 + tig + 4] * QSCALE);
    }

    float m_lo = -1e30f, m_hi = -1e30f, l_lo = 0.0f, l_hi = 0.0f;
    float o[8][4];
    #pragma unroll
    for (int nn = 0; nn < 8; nn++)
        #pragma unroll
        for (int j = 0; j < 4; j++) o[nn][j] = 0.0f;

    const int srcA = (lane & 28) | (tig >> 1);  // source lane for cols tig
    const int srcB = srcA + 2;                  // source lane for cols tig+4
    const bool sel = (tig & 1) != 0;

    const int nkb = S >> 6;
    for (int kb = 0; kb < nkb; kb++) {
        __syncthreads();
        // Cooperative K/V tile load (64 x 64), tf32-rounded, pad-68 rows.
        #pragma unroll
        for (int i = 0; i < 4; i++) {
            int idx = tid + i * 256;
            int r = idx >> 4, c4 = idx & 15;
            float4 k4 = *(const float4*)(Kb + (size_t)(kb*64 + r) * D_MODEL + c4*4);
            uint4 ku; ku.x = f2tf32(k4.x); ku.y = f2tf32(k4.y);
                      ku.z = f2tf32(k4.z); ku.w = f2tf32(k4.w);
            *(uint4*)&Kt[r * 68 + c4 * 4] = ku;
            float4 v4 = *(const float4*)(Vb + (size_t)(kb*64 + r) * D_MODEL + c4*4);
            uint4 vu; vu.x = f2tf32(v4.x); vu.y = f2tf32(v4.y);
                      vu.z = f2tf32(v4.z); vu.w = f2tf32(v4.w);
            *(uint4*)&Vs[r * 68 + c4 * 4] = vu;
        }
        __syncthreads();

        // ---- S = Q @ K^T : warp computes 16 x 64 scores ----
        float sv[8][4];
        #pragma unroll
        for (int nn = 0; nn < 8; nn++) {
            sv[nn][0] = sv[nn][1] = sv[nn][2] = sv[nn][3] = 0.0f;
            #pragma unroll
            for (int kk = 0; kk < 8; kk++) {
                uint32_t b0 = Kt[(nn*8 + gr) * 68 + kk*8 + tig];
                uint32_t b1 = Kt[(nn*8 + gr) * 68 + kk*8 + tig + 4];
                MMA_TF32(sv[nn], qf[kk], b0, b1);
            }
        }

        // ---- online softmax (rows gr and gr+8; quad-local reductions) ----
        float mx_lo = -1e30f, mx_hi = -1e30f;
        #pragma unroll
        for (int nn = 0; nn < 8; nn++) {
            mx_lo = fmaxf(mx_lo, fmaxf(sv[nn][0], sv[nn][1]));
            mx_hi = fmaxf(mx_hi, fmaxf(sv[nn][2], sv[nn][3]));
        }
        mx_lo = fmaxf(mx_lo, __shfl_xor_sync(0xffffffffu, mx_lo, 1));
        mx_lo = fmaxf(mx_lo, __shfl_xor_sync(0xffffffffu, mx_lo, 2));
        mx_hi = fmaxf(mx_hi, __shfl_xor_sync(0xffffffffu, mx_hi, 1));
        mx_hi = fmaxf(mx_hi, __shfl_xor_sync(0xffffffffu, mx_hi, 2));

        float mn_lo = fmaxf(m_lo, mx_lo);
        float mn_hi = fmaxf(m_hi, mx_hi);
        float al_lo = ex2f(m_lo - mn_lo);
        float al_hi = ex2f(m_hi - mn_hi);
        m_lo = mn_lo; m_hi = mn_hi;

        float rs_lo = 0.0f, rs_hi = 0.0f;
        #pragma unroll
        for (int nn = 0; nn < 8; nn++) {
            sv[nn][0] = ex2f(sv[nn][0] - mn_lo);
            sv[nn][1] = ex2f(sv[nn][1] - mn_lo);
            sv[nn][2] = ex2f(sv[nn][2] - mn_hi);
            sv[nn][3] = ex2f(sv[nn][3] - mn_hi);
            rs_lo += sv[nn][0] + sv[nn][1];
            rs_hi += sv[nn][2] + sv[nn][3];
        }
        rs_lo += __shfl_xor_sync(0xffffffffu, rs_lo, 1);
        rs_lo += __shfl_xor_sync(0xffffffffu, rs_lo, 2);
        rs_hi += __shfl_xor_sync(0xffffffffu, rs_hi, 1);
        rs_hi += __shfl_xor_sync(0xffffffffu, rs_hi, 2);
        l_lo = l_lo * al_lo + rs_lo;
        l_hi = l_hi * al_hi + rs_hi;

        #pragma unroll
        for (int nn = 0; nn < 8; nn++) {
            o[nn][0] *= al_lo; o[nn][1] *= al_lo;
            o[nn][2] *= al_hi; o[nn][3] *= al_hi;
        }

        // ---- O += P @ V : P C-frags -> A-frags via shuffles ----
        #pragma unroll
        for (int kk = 0; kk < 8; kk++) {
            float v00 = __shfl_sync(0xffffffffu, sv[kk][0], srcA);
            float v01 = __shfl_sync(0xffffffffu, sv[kk][1], srcA);
            float v10 = __shfl_sync(0xffffffffu, sv[kk][2], srcA);
            float v11 = __shfl_sync(0xffffffffu, sv[kk][3], srcA);
            float w00 = __shfl_sync(0xffffffffu, sv[kk][0], srcB);
            float w01 = __shfl_sync(0xffffffffu, sv[kk][1], srcB);
            float w10 = __shfl_sync(0xffffffffu, sv[kk][2], srcB);
            float w11 = __shfl_sync(0xffffffffu, sv[kk][3], srcB);
            uint32_t a[4];
            a[0] = __float_as_uint(sel ? v01 : v00);   // P(gr,   kk*8+tig)
            a[1] = __float_as_uint(sel ? v11 : v10);   // P(gr+8, kk*8+tig)
            a[2] = __float_as_uint(sel ? w01 : w00);   // P(gr,   kk*8+tig+4)
            a[3] = __float_as_uint(sel ? w11 : w10);   // P(gr+8, kk*8+tig+4)
            #pragma unroll
            for (int nn = 0; nn < 8; nn++) {
                uint32_t b0 = Vs[(kk*8 + tig)     * 68 + nn*8 + gr];
                uint32_t b1 = Vs[(kk*8 + tig + 4) * 68 + nn*8 + gr];
                MMA_TF32(o[nn], a, b0, b1);
            }
        }
    }

    // ---- epilogue: normalize, store (layout [B*S, D_MODEL]) ----
    const float inv_lo = 1.0f / l_lo;
    const float inv_hi = 1.0f / l_hi;
    float* Ob = O + ((size_t)b * S + q0) * D_MODEL + h * DK;
    #pragma unroll
    for (int nn = 0; nn < 8; nn++) {
        float2 lo; lo.x = o[nn][0] * inv_lo; lo.y = o[nn][1] * inv_lo;
        float2 hi; hi.x = o[nn][2] * inv_hi; hi.y = o[nn][3] * inv_hi;
        *(float2*)(Ob + (size_t)(m0 + gr)     * D_MODEL + nn*8 + tig*2) = lo;
        *(float2*)(Ob + (size_t)(m0 + gr + 8) * D_MODEL + nn*8 + tig*2) = hi;
    }
}

// ---------------------------------------------------------------------------
extern "C" void kernel_launch(void* const* d_in, const int* in_sizes, int n_in,
                              void* d_out, int out_size)
{
    (void)n_in; (void)out_size;
    const float* query = (const float*)d_in[0];
    const float* key   = (const float*)d_in[1];
    const float* value = (const float*)d_in[2];
    const float* Wq = (const float*)d_in[3];
    const float* bq = (const float*)d_in[4];
    const float* Wk = (const float*)d_in[5];
    const float* bk = (const float*)d_in[6];
    const float* Wv = (const float*)d_in[7];
    const float* bv = (const float*)d_in[8];
    const float* Wo = (const float*)d_in[9];
    const float* bo = (const float*)d_in[10];
    float* out = (float*)d_out;

    const int M = in_sizes[0] / D_MODEL;   // B*S = 8192
    const int S = M / BATCH;               // 4096

    float *pQ, *pK, *pV, *pAO;
    cudaGetSymbolAddress((void**)&pQ,  g_Q);
    cudaGetSymbolAddress((void**)&pK,  g_K);
    cudaGetSymbolAddress((void**)&pV,  g_V);
    cudaGetSymbolAddress((void**)&pAO, g_AO);

    dim3 gblk(D_MODEL / 128, M / 128);
    gemm_bias_kernel<<<gblk, 256>>>(query, Wq, bq, pQ, M, D_MODEL, D_MODEL);
    gemm_bias_kernel<<<gblk, 256>>>(key,   Wk, bk, pK, M, D_MODEL, D_MODEL);
    gemm_bias_kernel<<<gblk, 256>>>(value, Wv, bv, pV, M, D_MODEL, D_MODEL);

    flash_mma_kernel<<<dim3(S / 128, BATCH * N_HEADS), 256>>>(pQ, pK, pV, pAO, S);

    gemm_bias_kernel<<<gblk, 256>>>(pAO, Wo, bo, out, M, D_MODEL, D_MODEL);
}

// round 5
// speedup vs baseline: 1.8996x; 1.0504x over previous
#include <cuda_runtime.h>
#include <cstdint>

#define D_MODEL 1024
#define N_HEADS 16
#define DK 64
#define BATCH 2
#define MAX_S 4096

// Scratch: __device__ globals (allocation inside kernel_launch is forbidden).
__device__ float g_Q [BATCH * MAX_S * D_MODEL];
__device__ float g_K [BATCH * MAX_S * D_MODEL];
__device__ float g_V [BATCH * MAX_S * D_MODEL];
__device__ float g_AO[BATCH * MAX_S * D_MODEL];

// ---------------------------------------------------------------------------
// Helpers
// ---------------------------------------------------------------------------
__device__ __forceinline__ float ex2f(float x) {
    float y; asm("ex2.approx.ftz.f32 %0, %1;" : "=f"(y) : "f"(x)); return y;
}
__device__ __forceinline__ uint32_t f2tf32(float x) {
    uint32_t r; asm("cvt.rna.tf32.f32 %0, %1;" : "=r"(r) : "f"(x)); return r;
}

// mma.sync m16n8k8 tf32 (sm_80+, portable target): D += A*B, fp32 accum.
#define MMA_TF32(c, a, b0, b1) \
    asm volatile("mma.sync.aligned.m16n8k8.row.col.f32.tf32.tf32.f32 " \
        "{%0,%1,%2,%3}, {%4,%5,%6,%7}, {%8,%9}, {%0,%1,%2,%3};" \
        : "+f"((c)[0]), "+f"((c)[1]), "+f"((c)[2]), "+f"((c)[3]) \
        : "r"((a)[0]), "r"((a)[1]), "r"((a)[2]), "r"((a)[3]), \
          "r"(b0), "r"(b1))

// ---------------------------------------------------------------------------
// GEMM: C[M,N] = A[M,K] @ W[N,K]^T + bias   (Round-1 kernel, known-good)
// ---------------------------------------------------------------------------
__global__ __launch_bounds__(256, 2)
void gemm_bias_kernel(const float* __restrict__ A, const float* __restrict__ W,
                      const float* __restrict__ bias, float* __restrict__ C,
                      int M, int N, int K)
{
    __shared__ float As[16][128];
    __shared__ float Bs[16][128];

    const int tid = threadIdx.x;
    const int tx = tid & 15;
    const int ty = tid >> 4;
    const int m0 = blockIdx.y * 128;
    const int n0 = blockIdx.x * 128;
    const int lrow = tid >> 2;
    const int lk4  = tid & 3;

    float acc[8][8];
    #pragma unroll
    for (int i = 0; i < 8; i++)
        #pragma unroll
        for (int j = 0; j < 8; j++) acc[i][j] = 0.0f;

    for (int k0 = 0; k0 < K; k0 += 16) {
        #pragma unroll
        for (int v = 0; v < 2; v++) {
            int row = lrow + v * 64;
            float4 ta = *(const float4*)(A + (size_t)(m0 + row) * K + k0 + lk4 * 4);
            As[lk4*4+0][row] = ta.x; As[lk4*4+1][row] = ta.y;
            As[lk4*4+2][row] = ta.z; As[lk4*4+3][row] = ta.w;
            float4 tb = *(const float4*)(W + (size_t)(n0 + row) * K + k0 + lk4 * 4);
            Bs[lk4*4+0][row] = tb.x; Bs[lk4*4+1][row] = tb.y;
            Bs[lk4*4+2][row] = tb.z; Bs[lk4*4+3][row] = tb.w;
        }
        __syncthreads();
        #pragma unroll
        for (int kk = 0; kk < 16; kk++) {
            float a[8], b[8];
            *(float4*)&a[0] = *(const float4*)&As[kk][ty * 8];
            *(float4*)&a[4] = *(const float4*)&As[kk][ty * 8 + 4];
            *(float4*)&b[0] = *(const float4*)&Bs[kk][tx * 8];
            *(float4*)&b[4] = *(const float4*)&Bs[kk][tx * 8 + 4];
            #pragma unroll
            for (int i = 0; i < 8; i++)
                #pragma unroll
                for (int j = 0; j < 8; j++)
                    acc[i][j] = fmaf(a[i], b[j], acc[i][j]);
        }
        __syncthreads();
    }

    #pragma unroll
    for (int i = 0; i < 8; i++) {
        int m = m0 + ty * 8 + i;
        #pragma unroll
        for (int j4 = 0; j4 < 2; j4++) {
            int n = n0 + tx * 8 + j4 * 4;
            float4 bv = *(const float4*)(bias + n);
            float4 o;
            o.x = acc[i][j4*4+0] + bv.x; o.y = acc[i][j4*4+1] + bv.y;
            o.z = acc[i][j4*4+2] + bv.z; o.w = acc[i][j4*4+3] + bv.w;
            *(float4*)(C + (size_t)m * N + n) = o;
        }
    }
}

// ---------------------------------------------------------------------------
// Flash attention via mma.sync m16n8k8 tf32 — 4 warps x 32 q-rows.
// CTA = (b, h, 128-q tile). 128 threads = 4 warps; warp w owns q rows
// [w*32, w*32+32) as TWO m16 tiles sharing every B fragment (halves smem
// crossbar traffic vs 8x16). KV blocks of 64. Q fragments register-resident.
// K,V tiles in smem [64][68] (pad-68 => conflict-free fragment loads).
// Softmax quad-local; P C-frags -> A-frags via shuffles (no smem).
//
// Fragment maps (m16n8k8, lane: gr = lane>>2, tig = lane&3):
//   A(16x8 row):  a0=(gr,tig) a1=(gr+8,tig) a2=(gr,tig+4) a3=(gr+8,tig+4)
//   B(8x8 col):   b0=(k=tig, n=gr)  b1=(k=tig+4, n=gr)
//   C(16x8):      c0=(gr,2tig) c1=(gr,2tig+1) c2=(gr+8,2tig) c3=(gr+8,2tig+1)
// Row groups per lane: g0=gr, g1=gr+8, g2=gr+16, g3=gr+24 (frags [2g],[2g+1]).
// ---------------------------------------------------------------------------
__global__ __launch_bounds__(128, 2)
void flash_mma_kernel(const float* __restrict__ Q, const float* __restrict__ K,
                      const float* __restrict__ V, float* __restrict__ O, int S)
{
    __shared__ uint32_t Kt[64 * 68];
    __shared__ uint32_t Vs[64 * 68];

    const int tid  = threadIdx.x;
    const int wid  = tid >> 5;           // 0..3
    const int lane = tid & 31;
    const int gr   = lane >> 2;
    const int tig  = lane & 3;

    const int q0 = blockIdx.x * 128;
    const int b  = blockIdx.y >> 4;
    const int h  = blockIdx.y & 15;
    const int m0 = wid * 32;             // warp's q-row base within tile

    const float* Qb = Q + ((size_t)b * S + q0) * D_MODEL + h * DK;
    const float* Kb = K + (size_t)b * S * D_MODEL + h * DK;
    const float* Vb = V + (size_t)b * S * D_MODEL + h * DK;

    // Q fragments (2 m16 tiles): fold 1/sqrt(dk) * log2(e) for ex2 softmax.
    const float QSCALE = 0.125f * 1.4426950408889634f;
    uint32_t qf[8][8];
    #pragma unroll
    for (int kk = 0; kk < 8; kk++) {
        const int c0 = kk * 8 + tig;
        qf[kk][0] = f2tf32(Qb[(size_t)(m0 + gr)      * D_MODEL + c0]     * QSCALE);
        qf[kk][1] = f2tf32(Qb[(size_t)(m0 + gr + 8)  * D_MODEL + c0]     * QSCALE);
        qf[kk][2] = f2tf32(Qb[(size_t)(m0 + gr)      * D_MODEL + c0 + 4] * QSCALE);
        qf[kk][3] = f2tf32(Qb[(size_t)(m0 + gr + 8)  * D_MODEL + c0 + 4] * QSCALE);
        qf[kk][4] = f2tf32(Qb[(size_t)(m0 + gr + 16) * D_MODEL + c0]     * QSCALE);
        qf[kk][5] = f2tf32(Qb[(size_t)(m0 + gr + 24) * D_MODEL + c0]     * QSCALE);
        qf[kk][6] = f2tf32(Qb[(size_t)(m0 + gr + 16) * D_MODEL + c0 + 4] * QSCALE);
        qf[kk][7] = f2tf32(Qb[(size_t)(m0 + gr + 24) * D_MODEL + c0 + 4] * QSCALE);
    }

    float m_g[4], l_g[4];
    #pragma unroll
    for (int g = 0; g < 4; g++) { m_g[g] = -1e30f; l_g[g] = 0.0f; }
    float o[8][8];
    #pragma unroll
    for (int nn = 0; nn < 8; nn++)
        #pragma unroll
        for (int j = 0; j < 8; j++) o[nn][j] = 0.0f;

    const int srcA = (lane & 28) | (tig >> 1);  // source lane for col tig
    const int srcB = srcA + 2;                  // source lane for col tig+4
    const bool sel = (tig & 1) != 0;

    const int nkb = S >> 6;
    for (int kb = 0; kb < nkb; kb++) {
        __syncthreads();
        // Cooperative K/V tile load (64 x 64), tf32-rounded, pad-68 rows.
        #pragma unroll
        for (int i = 0; i < 8; i++) {
            int idx = tid + i * 128;
            int r = idx >> 4, c4 = idx & 15;
            float4 k4 = *(const float4*)(Kb + (size_t)(kb*64 + r) * D_MODEL + c4*4);
            uint4 ku; ku.x = f2tf32(k4.x); ku.y = f2tf32(k4.y);
                      ku.z = f2tf32(k4.z); ku.w = f2tf32(k4.w);
            *(uint4*)&Kt[r * 68 + c4 * 4] = ku;
            float4 v4 = *(const float4*)(Vb + (size_t)(kb*64 + r) * D_MODEL + c4*4);
            uint4 vu; vu.x = f2tf32(v4.x); vu.y = f2tf32(v4.y);
                      vu.z = f2tf32(v4.z); vu.w = f2tf32(v4.w);
            *(uint4*)&Vs[r * 68 + c4 * 4] = vu;
        }
        __syncthreads();

        // ---- S = Q @ K^T : warp computes 32 x 64 scores ----
        float sv[8][8];
        #pragma unroll
        for (int nn = 0; nn < 8; nn++) {
            #pragma unroll
            for (int j = 0; j < 8; j++) sv[nn][j] = 0.0f;
            #pragma unroll
            for (int kk = 0; kk < 8; kk++) {
                uint32_t b0 = Kt[(nn*8 + gr) * 68 + kk*8 + tig];
                uint32_t b1 = Kt[(nn*8 + gr) * 68 + kk*8 + tig + 4];
                MMA_TF32(&sv[nn][0], &qf[kk][0], b0, b1);   // rows m0..m0+16
                MMA_TF32(&sv[nn][4], &qf[kk][4], b0, b1);   // rows m0+16..m0+32
            }
        }

        // ---- online softmax: 4 row groups, quad-local reductions ----
        float al[4];
        #pragma unroll
        for (int g = 0; g < 4; g++) {
            float mx = -1e30f;
            #pragma unroll
            for (int nn = 0; nn < 8; nn++)
                mx = fmaxf(mx, fmaxf(sv[nn][2*g], sv[nn][2*g+1]));
            mx = fmaxf(mx, __shfl_xor_sync(0xffffffffu, mx, 1));
            mx = fmaxf(mx, __shfl_xor_sync(0xffffffffu, mx, 2));
            float mn = fmaxf(m_g[g], mx);
            al[g] = ex2f(m_g[g] - mn);
            m_g[g] = mn;
            float rs = 0.0f;
            #pragma unroll
            for (int nn = 0; nn < 8; nn++) {
                sv[nn][2*g]   = ex2f(sv[nn][2*g]   - mn);
                sv[nn][2*g+1] = ex2f(sv[nn][2*g+1] - mn);
                rs += sv[nn][2*g] + sv[nn][2*g+1];
            }
            rs += __shfl_xor_sync(0xffffffffu, rs, 1);
            rs += __shfl_xor_sync(0xffffffffu, rs, 2);
            l_g[g] = l_g[g] * al[g] + rs;
        }
        #pragma unroll
        for (int nn = 0; nn < 8; nn++)
            #pragma unroll
            for (int g = 0; g < 4; g++) {
                o[nn][2*g]   *= al[g];
                o[nn][2*g+1] *= al[g];
            }

        // ---- O += P @ V : P C-frags -> A-frags via shuffles ----
        #pragma unroll
        for (int kk = 0; kk < 8; kk++) {
            uint32_t a[8];
            #pragma unroll
            for (int t = 0; t < 2; t++) {
                float v00 = __shfl_sync(0xffffffffu, sv[kk][t*4+0], srcA);
                float v01 = __shfl_sync(0xffffffffu, sv[kk][t*4+1], srcA);
                float v10 = __shfl_sync(0xffffffffu, sv[kk][t*4+2], srcA);
                float v11 = __shfl_sync(0xffffffffu, sv[kk][t*4+3], srcA);
                float w00 = __shfl_sync(0xffffffffu, sv[kk][t*4+0], srcB);
                float w01 = __shfl_sync(0xffffffffu, sv[kk][t*4+1], srcB);
                float w10 = __shfl_sync(0xffffffffu, sv[kk][t*4+2], srcB);
                float w11 = __shfl_sync(0xffffffffu, sv[kk][t*4+3], srcB);
                a[t*4+0] = __float_as_uint(sel ? v01 : v00);
                a[t*4+1] = __float_as_uint(sel ? v11 : v10);
                a[t*4+2] = __float_as_uint(sel ? w01 : w00);
                a[t*4+3] = __float_as_uint(sel ? w11 : w10);
            }
            #pragma unroll
            for (int nn = 0; nn < 8; nn++) {
                uint32_t b0 = Vs[(kk*8 + tig)     * 68 + nn*8 + gr];
                uint32_t b1 = Vs[(kk*8 + tig + 4) * 68 + nn*8 + gr];
                MMA_TF32(&o[nn][0], &a[0], b0, b1);
                MMA_TF32(&o[nn][4], &a[4], b0, b1);
            }
        }
    }

    // ---- epilogue: normalize, store (layout [B*S, D_MODEL]) ----
    float inv[4];
    #pragma unroll
    for (int g = 0; g < 4; g++) inv[g] = 1.0f / l_g[g];
    float* Ob = O + ((size_t)b * S + q0) * D_MODEL + h * DK;
    const int rowg[4] = { m0 + gr, m0 + gr + 8, m0 + gr + 16, m0 + gr + 24 };
    #pragma unroll
    for (int nn = 0; nn < 8; nn++) {
        #pragma unroll
        for (int g = 0; g < 4; g++) {
            float2 val;
            val.x = o[nn][2*g]   * inv[g];
            val.y = o[nn][2*g+1] * inv[g];
            *(float2*)(Ob + (size_t)rowg[g] * D_MODEL + nn*8 + tig*2) = val;
        }
    }
}

// ---------------------------------------------------------------------------
extern "C" void kernel_launch(void* const* d_in, const int* in_sizes, int n_in,
                              void* d_out, int out_size)
{
    (void)n_in; (void)out_size;
    const float* query = (const float*)d_in[0];
    const float* key   = (const float*)d_in[1];
    const float* value = (const float*)d_in[2];
    const float* Wq = (const float*)d_in[3];
    const float* bq = (const float*)d_in[4];
    const float* Wk = (const float*)d_in[5];
    const float* bk = (const float*)d_in[6];
    const float* Wv = (const float*)d_in[7];
    const float* bv = (const float*)d_in[8];
    const float* Wo = (const float*)d_in[9];
    const float* bo = (const float*)d_in[10];
    float* out = (float*)d_out;

    const int M = in_sizes[0] / D_MODEL;   // B*S = 8192
    const int S = M / BATCH;               // 4096

    float *pQ, *pK, *pV, *pAO;
    cudaGetSymbolAddress((void**)&pQ,  g_Q);
    cudaGetSymbolAddress((void**)&pK,  g_K);
    cudaGetSymbolAddress((void**)&pV,  g_V);
    cudaGetSymbolAddress((void**)&pAO, g_AO);

    dim3 gblk(D_MODEL / 128, M / 128);
    gemm_bias_kernel<<<gblk, 256>>>(query, Wq, bq, pQ, M, D_MODEL, D_MODEL);
    gemm_bias_kernel<<<gblk, 256>>>(key,   Wk, bk, pK, M, D_MODEL, D_MODEL);
    gemm_bias_kernel<<<gblk, 256>>>(value, Wv, bv, pV, M, D_MODEL, D_MODEL);

    flash_mma_kernel<<<dim3(S / 128, BATCH * N_HEADS), 128>>>(pQ, pK, pV, pAO, S);

    gemm_bias_kernel<<<gblk, 256>>>(pAO, Wo, bo, out, M, D_MODEL, D_MODEL);
}

// round 6
// speedup vs baseline: 2.7036x; 1.4232x over previous
#include <cuda_runtime.h>
#include <cstdint>

#define D_MODEL 1024
#define N_HEADS 16
#define DK 64
#define BATCH 2
#define MAX_S 4096

// Scratch: __device__ globals (allocation inside kernel_launch is forbidden).
__device__ float g_Q [BATCH * MAX_S * D_MODEL];
__device__ float g_K [BATCH * MAX_S * D_MODEL];
__device__ float g_V [BATCH * MAX_S * D_MODEL];
__device__ float g_AO[BATCH * MAX_S * D_MODEL];

// ---------------------------------------------------------------------------
// Helpers
// ---------------------------------------------------------------------------
__device__ __forceinline__ float ex2f(float x) {
    float y; asm("ex2.approx.ftz.f32 %0, %1;" : "=f"(y) : "f"(x)); return y;
}
__device__ __forceinline__ uint32_t f2tf32(float x) {
    uint32_t r; asm("cvt.rna.tf32.f32 %0, %1;" : "=r"(r) : "f"(x)); return r;
}

// mma.sync m16n8k8 tf32 (sm_80+, portable target): D += A*B, fp32 accum.
#define MMA_TF32(c, a, b0, b1) \
    asm volatile("mma.sync.aligned.m16n8k8.row.col.f32.tf32.tf32.f32 " \
        "{%0,%1,%2,%3}, {%4,%5,%6,%7}, {%8,%9}, {%0,%1,%2,%3};" \
        : "+f"((c)[0]), "+f"((c)[1]), "+f"((c)[2]), "+f"((c)[3]) \
        : "r"((a)[0]), "r"((a)[1]), "r"((a)[2]), "r"((a)[3]), \
          "r"(b0), "r"(b1))

// ---------------------------------------------------------------------------
// Projection GEMM via mma.sync tf32, 2-pass A-split for near-fp32 accuracy.
// C[M,N] = A[M,K] @ W[N,K]^T + bias.
// CTA: 128x128 tile, BK=32, 256 threads = 8 warps in 4x2 grid; each warp
// computes 32x64 (2 m16 tiles x 8 n8 tiles). A stored in smem as (hi, lo)
// tf32 pair: a = hi + lo, accumulate A_hi*W + A_lo*W (fp32 accumulators).
// Pad-36 rows => fragment LDS banks = 4*gr + tig, conflict-free.
// ---------------------------------------------------------------------------
#define GP 36
#define GEMM_SMEM (3 * 128 * GP * 4)

__global__ __launch_bounds__(256, 2)
void gemm_tf32_kernel(const float* __restrict__ A, const float* __restrict__ W,
                      const float* __restrict__ bias, float* __restrict__ C,
                      int M, int N, int K)
{
    extern __shared__ uint32_t sm[];
    uint32_t* Ah = sm;                  // 128*GP
    uint32_t* Al = sm + 128 * GP;       // 128*GP
    uint32_t* Ws = sm + 2 * 128 * GP;   // 128*GP

    const int tid  = threadIdx.x;
    const int wid  = tid >> 5;
    const int lane = tid & 31;
    const int gr   = lane >> 2;
    const int tig  = lane & 3;
    const int m0 = blockIdx.y * 128;
    const int n0 = blockIdx.x * 128;
    const int wm = (wid >> 1) * 32;     // warp row base in tile
    const int wn = (wid & 1) * 64;      // warp col base in tile

    float c[2][8][4];
    #pragma unroll
    for (int mt = 0; mt < 2; mt++)
        #pragma unroll
        for (int nn = 0; nn < 8; nn++)
            #pragma unroll
            for (int j = 0; j < 4; j++) c[mt][nn][j] = 0.0f;

    for (int k0 = 0; k0 < K; k0 += 32) {
        __syncthreads();
        #pragma unroll
        for (int i = 0; i < 4; i++) {
            int idx = tid + i * 256;
            int r  = idx >> 3;
            int c4 = (idx & 7) * 4;
            float4 a4 = *(const float4*)(A + (size_t)(m0 + r) * K + k0 + c4);
            uint4 hi, lo;
            hi.x = f2tf32(a4.x); lo.x = f2tf32(a4.x - __uint_as_float(hi.x));
            hi.y = f2tf32(a4.y); lo.y = f2tf32(a4.y - __uint_as_float(hi.y));
            hi.z = f2tf32(a4.z); lo.z = f2tf32(a4.z - __uint_as_float(hi.z));
            hi.w = f2tf32(a4.w); lo.w = f2tf32(a4.w - __uint_as_float(hi.w));
            *(uint4*)&Ah[r * GP + c4] = hi;
            *(uint4*)&Al[r * GP + c4] = lo;
            float4 w4 = *(const float4*)(W + (size_t)(n0 + r) * K + k0 + c4);
            uint4 wt;
            wt.x = f2tf32(w4.x); wt.y = f2tf32(w4.y);
            wt.z = f2tf32(w4.z); wt.w = f2tf32(w4.w);
            *(uint4*)&Ws[r * GP + c4] = wt;
        }
        __syncthreads();

        #pragma unroll
        for (int kk = 0; kk < 4; kk++) {
            const int kb = kk * 8;
            uint32_t bf0[8], bf1[8];
            #pragma unroll
            for (int nn = 0; nn < 8; nn++) {
                bf0[nn] = Ws[(wn + nn*8 + gr) * GP + kb + tig];
                bf1[nn] = Ws[(wn + nn*8 + gr) * GP + kb + tig + 4];
            }
            #pragma unroll
            for (int mt = 0; mt < 2; mt++) {
                const int R = wm + mt * 16 + gr;
                uint32_t ah[4], al[4];
                ah[0] = Ah[R * GP + kb + tig];
                ah[1] = Ah[(R + 8) * GP + kb + tig];
                ah[2] = Ah[R * GP + kb + tig + 4];
                ah[3] = Ah[(R + 8) * GP + kb + tig + 4];
                al[0] = Al[R * GP + kb + tig];
                al[1] = Al[(R + 8) * GP + kb + tig];
                al[2] = Al[R * GP + kb + tig + 4];
                al[3] = Al[(R + 8) * GP + kb + tig + 4];
                #pragma unroll
                for (int nn = 0; nn < 8; nn++) {
                    MMA_TF32(c[mt][nn], ah, bf0[nn], bf1[nn]);
                    MMA_TF32(c[mt][nn], al, bf0[nn], bf1[nn]);
                }
            }
        }
    }

    // Epilogue: add bias (fp32), store.
    #pragma unroll
    for (int mt = 0; mt < 2; mt++) {
        int R = m0 + wm + mt * 16 + gr;
        #pragma unroll
        for (int nn = 0; nn < 8; nn++) {
            int col = n0 + wn + nn * 8 + tig * 2;
            float2 bv = *(const float2*)(bias + col);
            float2 v0; v0.x = c[mt][nn][0] + bv.x; v0.y = c[mt][nn][1] + bv.y;
            float2 v1; v1.x = c[mt][nn][2] + bv.x; v1.y = c[mt][nn][3] + bv.y;
            *(float2*)(C + (size_t)R * N + col) = v0;
            *(float2*)(C + (size_t)(R + 8) * N + col) = v1;
        }
    }
}

// ---------------------------------------------------------------------------
// Flash attention via mma.sync m16n8k8 tf32 — 4 warps x 32 q-rows.
// (Unchanged from Round 5; passing at rel_err 5.4e-4.)
// ---------------------------------------------------------------------------
__global__ __launch_bounds__(128, 2)
void flash_mma_kernel(const float* __restrict__ Q, const float* __restrict__ K,
                      const float* __restrict__ V, float* __restrict__ O, int S)
{
    __shared__ uint32_t Kt[64 * 68];
    __shared__ uint32_t Vs[64 * 68];

    const int tid  = threadIdx.x;
    const int wid  = tid >> 5;           // 0..3
    const int lane = tid & 31;
    const int gr   = lane >> 2;
    const int tig  = lane & 3;

    const int q0 = blockIdx.x * 128;
    const int b  = blockIdx.y >> 4;
    const int h  = blockIdx.y & 15;
    const int m0 = wid * 32;             // warp's q-row base within tile

    const float* Qb = Q + ((size_t)b * S + q0) * D_MODEL + h * DK;
    const float* Kb = K + (size_t)b * S * D_MODEL + h * DK;
    const float* Vb = V + (size_t)b * S * D_MODEL + h * DK;

    // Q fragments (2 m16 tiles): fold 1/sqrt(dk) * log2(e) for ex2 softmax.
    const float QSCALE = 0.125f * 1.4426950408889634f;
    uint32_t qf[8][8];
    #pragma unroll
    for (int kk = 0; kk < 8; kk++) {
        const int c0 = kk * 8 + tig;
        qf[kk][0] = f2tf32(Qb[(size_t)(m0 + gr)      * D_MODEL + c0]     * QSCALE);
        qf[kk][1] = f2tf32(Qb[(size_t)(m0 + gr + 8)  * D_MODEL + c0]     * QSCALE);
        qf[kk][2] = f2tf32(Qb[(size_t)(m0 + gr)      * D_MODEL + c0 + 4] * QSCALE);
        qf[kk][3] = f2tf32(Qb[(size_t)(m0 + gr + 8)  * D_MODEL + c0 + 4] * QSCALE);
        qf[kk][4] = f2tf32(Qb[(size_t)(m0 + gr + 16) * D_MODEL + c0]     * QSCALE);
        qf[kk][5] = f2tf32(Qb[(size_t)(m0 + gr + 24) * D_MODEL + c0]     * QSCALE);
        qf[kk][6] = f2tf32(Qb[(size_t)(m0 + gr + 16) * D_MODEL + c0 + 4] * QSCALE);
        qf[kk][7] = f2tf32(Qb[(size_t)(m0 + gr + 24) * D_MODEL + c0 + 4] * QSCALE);
    }

    float m_g[4], l_g[4];
    #pragma unroll
    for (int g = 0; g < 4; g++) { m_g[g] = -1e30f; l_g[g] = 0.0f; }
    float o[8][8];
    #pragma unroll
    for (int nn = 0; nn < 8; nn++)
        #pragma unroll
        for (int j = 0; j < 8; j++) o[nn][j] = 0.0f;

    const int srcA = (lane & 28) | (tig >> 1);  // source lane for col tig
    const int srcB = srcA + 2;                  // source lane for col tig+4
    const bool sel = (tig & 1) != 0;

    const int nkb = S >> 6;
    for (int kb = 0; kb < nkb; kb++) {
        __syncthreads();
        // Cooperative K/V tile load (64 x 64), tf32-rounded, pad-68 rows.
        #pragma unroll
        for (int i = 0; i < 8; i++) {
            int idx = tid + i * 128;
            int r = idx >> 4, c4 = idx & 15;
            float4 k4 = *(const float4*)(Kb + (size_t)(kb*64 + r) * D_MODEL + c4*4);
            uint4 ku; ku.x = f2tf32(k4.x); ku.y = f2tf32(k4.y);
                      ku.z = f2tf32(k4.z); ku.w = f2tf32(k4.w);
            *(uint4*)&Kt[r * 68 + c4 * 4] = ku;
            float4 v4 = *(const float4*)(Vb + (size_t)(kb*64 + r) * D_MODEL + c4*4);
            uint4 vu; vu.x = f2tf32(v4.x); vu.y = f2tf32(v4.y);
                      vu.z = f2tf32(v4.z); vu.w = f2tf32(v4.w);
            *(uint4*)&Vs[r * 68 + c4 * 4] = vu;
        }
        __syncthreads();

        // ---- S = Q @ K^T : warp computes 32 x 64 scores ----
        float sv[8][8];
        #pragma unroll
        for (int nn = 0; nn < 8; nn++) {
            #pragma unroll
            for (int j = 0; j < 8; j++) sv[nn][j] = 0.0f;
            #pragma unroll
            for (int kk = 0; kk < 8; kk++) {
                uint32_t b0 = Kt[(nn*8 + gr) * 68 + kk*8 + tig];
                uint32_t b1 = Kt[(nn*8 + gr) * 68 + kk*8 + tig + 4];
                MMA_TF32(&sv[nn][0], &qf[kk][0], b0, b1);   // rows m0..m0+16
                MMA_TF32(&sv[nn][4], &qf[kk][4], b0, b1);   // rows m0+16..m0+32
            }
        }

        // ---- online softmax: 4 row groups, quad-local reductions ----
        float al[4];
        #pragma unroll
        for (int g = 0; g < 4; g++) {
            float mx = -1e30f;
            #pragma unroll
            for (int nn = 0; nn < 8; nn++)
                mx = fmaxf(mx, fmaxf(sv[nn][2*g], sv[nn][2*g+1]));
            mx = fmaxf(mx, __shfl_xor_sync(0xffffffffu, mx, 1));
            mx = fmaxf(mx, __shfl_xor_sync(0xffffffffu, mx, 2));
            float mn = fmaxf(m_g[g], mx);
            al[g] = ex2f(m_g[g] - mn);
            m_g[g] = mn;
            float rs = 0.0f;
            #pragma unroll
            for (int nn = 0; nn < 8; nn++) {
                sv[nn][2*g]   = ex2f(sv[nn][2*g]   - mn);
                sv[nn][2*g+1] = ex2f(sv[nn][2*g+1] - mn);
                rs += sv[nn][2*g] + sv[nn][2*g+1];
            }
            rs += __shfl_xor_sync(0xffffffffu, rs, 1);
            rs += __shfl_xor_sync(0xffffffffu, rs, 2);
            l_g[g] = l_g[g] * al[g] + rs;
        }
        #pragma unroll
        for (int nn = 0; nn < 8; nn++)
            #pragma unroll
            for (int g = 0; g < 4; g++) {
                o[nn][2*g]   *= al[g];
                o[nn][2*g+1] *= al[g];
            }

        // ---- O += P @ V : P C-frags -> A-frags via shuffles ----
        #pragma unroll
        for (int kk = 0; kk < 8; kk++) {
            uint32_t a[8];
            #pragma unroll
            for (int t = 0; t < 2; t++) {
                float v00 = __shfl_sync(0xffffffffu, sv[kk][t*4+0], srcA);
                float v01 = __shfl_sync(0xffffffffu, sv[kk][t*4+1], srcA);
                float v10 = __shfl_sync(0xffffffffu, sv[kk][t*4+2], srcA);
                float v11 = __shfl_sync(0xffffffffu, sv[kk][t*4+3], srcA);
                float w00 = __shfl_sync(0xffffffffu, sv[kk][t*4+0], srcB);
                float w01 = __shfl_sync(0xffffffffu, sv[kk][t*4+1], srcB);
                float w10 = __shfl_sync(0xffffffffu, sv[kk][t*4+2], srcB);
                float w11 = __shfl_sync(0xffffffffu, sv[kk][t*4+3], srcB);
                a[t*4+0] = __float_as_uint(sel ? v01 : v00);
                a[t*4+1] = __float_as_uint(sel ? v11 : v10);
                a[t*4+2] = __float_as_uint(sel ? w01 : w00);
                a[t*4+3] = __float_as_uint(sel ? w11 : w10);
            }
            #pragma unroll
            for (int nn = 0; nn < 8; nn++) {
                uint32_t b0 = Vs[(kk*8 + tig)     * 68 + nn*8 + gr];
                uint32_t b1 = Vs[(kk*8 + tig + 4) * 68 + nn*8 + gr];
                MMA_TF32(&o[nn][0], &a[0], b0, b1);
                MMA_TF32(&o[nn][4], &a[4], b0, b1);
            }
        }
    }

    // ---- epilogue: normalize, store (layout [B*S, D_MODEL]) ----
    float inv[4];
    #pragma unroll
    for (int g = 0; g < 4; g++) inv[g] = 1.0f / l_g[g];
    float* Ob = O + ((size_t)b * S + q0) * D_MODEL + h * DK;
    const int rowg[4] = { m0 + gr, m0 + gr + 8, m0 + gr + 16, m0 + gr + 24 };
    #pragma unroll
    for (int nn = 0; nn < 8; nn++) {
        #pragma unroll
        for (int g = 0; g < 4; g++) {
            float2 val;
            val.x = o[nn][2*g]   * inv[g];
            val.y = o[nn][2*g+1] * inv[g];
            *(float2*)(Ob + (size_t)rowg[g] * D_MODEL + nn*8 + tig*2) = val;
        }
    }
}

// ---------------------------------------------------------------------------
extern "C" void kernel_launch(void* const* d_in, const int* in_sizes, int n_in,
                              void* d_out, int out_size)
{
    (void)n_in; (void)out_size;
    const float* query = (const float*)d_in[0];
    const float* key   = (const float*)d_in[1];
    const float* value = (const float*)d_in[2];
    const float* Wq = (const float*)d_in[3];
    const float* bq = (const float*)d_in[4];
    const float* Wk = (const float*)d_in[5];
    const float* bk = (const float*)d_in[6];
    const float* Wv = (const float*)d_in[7];
    const float* bv = (const float*)d_in[8];
    const float* Wo = (const float*)d_in[9];
    const float* bo = (const float*)d_in[10];
    float* out = (float*)d_out;

    const int M = in_sizes[0] / D_MODEL;   // B*S = 8192
    const int S = M / BATCH;               // 4096

    float *pQ, *pK, *pV, *pAO;
    cudaGetSymbolAddress((void**)&pQ,  g_Q);
    cudaGetSymbolAddress((void**)&pK,  g_K);
    cudaGetSymbolAddress((void**)&pV,  g_V);
    cudaGetSymbolAddress((void**)&pAO, g_AO);

    cudaFuncSetAttribute(gemm_tf32_kernel,
                         cudaFuncAttributeMaxDynamicSharedMemorySize, GEMM_SMEM);

    dim3 gblk(D_MODEL / 128, M / 128);   // (8, 64)
    gemm_tf32_kernel<<<gblk, 256, GEMM_SMEM>>>(query, Wq, bq, pQ, M, D_MODEL, D_MODEL);
    gemm_tf32_kernel<<<gblk, 256, GEMM_SMEM>>>(key,   Wk, bk, pK, M, D_MODEL, D_MODEL);
    gemm_tf32_kernel<<<gblk, 256, GEMM_SMEM>>>(value, Wv, bv, pV, M, D_MODEL, D_MODEL);

    flash_mma_kernel<<<dim3(S / 128, BATCH * N_HEADS), 128>>>(pQ, pK, pV, pAO, S);

    gemm_tf32_kernel<<<gblk, 256, GEMM_SMEM>>>(pAO, Wo, bo, out, M, D_MODEL, D_MODEL);
}

// round 7
// speedup vs baseline: 2.8093x; 1.0391x over previous
#include <cuda_runtime.h>
#include <cstdint>

#define D_MODEL 1024
#define N_HEADS 16
#define DK 64
#define BATCH 2
#define MAX_S 4096

// Scratch: __device__ globals (allocation inside kernel_launch is forbidden).
__device__ float    g_Q [BATCH * MAX_S * D_MODEL];
__device__ float    g_K [BATCH * MAX_S * D_MODEL];
__device__ float    g_V [BATCH * MAX_S * D_MODEL];
__device__ uint32_t g_hi[BATCH * MAX_S * D_MODEL];   // tf32 bits, A-split high
__device__ uint32_t g_lo[BATCH * MAX_S * D_MODEL];   // tf32 bits, A-split low
__device__ uint32_t g_Wt[D_MODEL * D_MODEL];         // tf32 bits, weight

// ---------------------------------------------------------------------------
// Helpers
// ---------------------------------------------------------------------------
__device__ __forceinline__ float ex2f(float x) {
    float y; asm("ex2.approx.ftz.f32 %0, %1;" : "=f"(y) : "f"(x)); return y;
}
__device__ __forceinline__ uint32_t f2tf32(float x) {
    uint32_t r; asm("cvt.rna.tf32.f32 %0, %1;" : "=r"(r) : "f"(x)); return r;
}
__device__ __forceinline__ uint32_t smem_to_u32(const void* p) {
    uint32_t a;
    asm("{ .reg .u64 t; cvta.to.shared.u64 t, %1; cvt.u32.u64 %0, t; }"
        : "=r"(a) : "l"(p));
    return a;
}
#define CP_ASYNC16(dst, src) \
    asm volatile("cp.async.cg.shared.global [%0], [%1], 16;" \
        :: "r"(dst), "l"(src) : "memory")
#define CP_COMMIT()  asm volatile("cp.async.commit_group;" ::: "memory")
#define CP_WAIT0()   asm volatile("cp.async.wait_group 0;" ::: "memory")

// mma.sync m16n8k8 tf32 (sm_80+, portable target): D += A*B, fp32 accum.
#define MMA_TF32(c, a, b0, b1) \
    asm volatile("mma.sync.aligned.m16n8k8.row.col.f32.tf32.tf32.f32 " \
        "{%0,%1,%2,%3}, {%4,%5,%6,%7}, {%8,%9}, {%0,%1,%2,%3};" \
        : "+f"((c)[0]), "+f"((c)[1]), "+f"((c)[2]), "+f"((c)[3]) \
        : "r"((a)[0]), "r"((a)[1]), "r"((a)[2]), "r"((a)[3]), \
          "r"(b0), "r"(b1))

// ---------------------------------------------------------------------------
// split: X (fp32) -> hi, lo tf32-bit pair (a = hi + lo to ~21 mantissa bits)
// ---------------------------------------------------------------------------
__global__ void split_tf32_kernel(const float* __restrict__ X,
                                  uint32_t* __restrict__ hi,
                                  uint32_t* __restrict__ lo)
{
    int i = blockIdx.x * 256 + threadIdx.x;
    float4 x = ((const float4*)X)[i];
    uint4 h, l;
    h.x = f2tf32(x.x); l.x = f2tf32(x.x - __uint_as_float(h.x));
    h.y = f2tf32(x.y); l.y = f2tf32(x.y - __uint_as_float(h.y));
    h.z = f2tf32(x.z); l.z = f2tf32(x.z - __uint_as_float(h.z));
    h.w = f2tf32(x.w); l.w = f2tf32(x.w - __uint_as_float(h.w));
    ((uint4*)hi)[i] = h;
    ((uint4*)lo)[i] = l;
}

__global__ void cvt_w_kernel(const float* __restrict__ W, uint32_t* __restrict__ Wt)
{
    int i = blockIdx.x * 256 + threadIdx.x;
    float4 w = ((const float4*)W)[i];
    uint4 t;
    t.x = f2tf32(w.x); t.y = f2tf32(w.y); t.z = f2tf32(w.z); t.w = f2tf32(w.w);
    ((uint4*)Wt)[i] = t;
}

// ---------------------------------------------------------------------------
// Projection GEMM v2: C[M,N] = (Ahi+Alo)[M,K] @ Wt[N,K]^T + bias.
// 128x128 tile, BK=32, 256 threads = 8 warps (4x2); warp tile 32x64.
// cp.async double-buffered (2 stages x 3 tiles x 16KB = 96KB smem);
// XOR-swizzled tiles (seg ^= r&7) => conflict-free fragment LDS.
// Inner loop is pure LDS + HMMA (all conversion precomputed).
// ---------------------------------------------------------------------------
#define GEMM_SMEM (2 * 3 * 16384)

// u32 index of element (r, c) in a swizzled 128x32 tile.
__device__ __forceinline__ int sidx(int r, int c) {
    return r * 32 + ((((c >> 2) ^ (r & 7))) << 2) + (c & 3);
}

__global__ __launch_bounds__(256, 2)
void gemm_tf32_kernel(const uint32_t* __restrict__ Ahi,
                      const uint32_t* __restrict__ Alo,
                      const uint32_t* __restrict__ Wt,
                      const float* __restrict__ bias, float* __restrict__ C,
                      int M, int N, int K)
{
    extern __shared__ uint32_t sm[];
    const uint32_t sbase = smem_to_u32(sm);

    const int tid  = threadIdx.x;
    const int wid  = tid >> 5;
    const int lane = tid & 31;
    const int gr   = lane >> 2;
    const int tig  = lane & 3;
    const int m0 = blockIdx.y * 128;
    const int n0 = blockIdx.x * 128;
    const int wm = (wid >> 1) * 32;
    const int wn = (wid & 1) * 64;

    // Per-thread copy slice: 4 (row, seg) pairs per tile per stage.
    const int cr0 = tid >> 3;        // rows tid/8 + {0,32,64,96}
    const int cs  = tid & 7;         // 16B segment 0..7

    float c[2][8][4];
    #pragma unroll
    for (int mt = 0; mt < 2; mt++)
        #pragma unroll
        for (int nn = 0; nn < 8; nn++)
            #pragma unroll
            for (int j = 0; j < 4; j++) c[mt][nn][j] = 0.0f;

    // Issue one stage of cp.async copies (Ahi, Alo, Wt tiles) into buffer `buf`.
    auto issue = [&](int k0, int buf) {
        const uint32_t base = sbase + buf * 49152;
        #pragma unroll
        for (int j = 0; j < 4; j++) {
            int r = cr0 + j * 32;
            uint32_t sw = (uint32_t)(r * 128 + ((cs ^ (r & 7)) << 4));
            const uint32_t* sH = Ahi + (size_t)(m0 + r) * K + k0 + cs * 4;
            const uint32_t* sL = Alo + (size_t)(m0 + r) * K + k0 + cs * 4;
            const uint32_t* sW = Wt  + (size_t)(n0 + r) * K + k0 + cs * 4;
            CP_ASYNC16(base + sw,         sH);
            CP_ASYNC16(base + 16384 + sw, sL);
            CP_ASYNC16(base + 32768 + sw, sW);
        }
        CP_COMMIT();
    };

    issue(0, 0);

    int buf = 0;
    for (int k0 = 0; k0 < K; k0 += 32, buf ^= 1) {
        CP_WAIT0();
        __syncthreads();
        if (k0 + 32 < K) issue(k0 + 32, buf ^ 1);

        const uint32_t* Hb = sm + buf * 12288;
        const uint32_t* Lb = Hb + 4096;
        const uint32_t* Wb = Hb + 8192;

        #pragma unroll
        for (int kk = 0; kk < 4; kk++) {
            const int kb = kk * 8;
            uint32_t bf0[8], bf1[8];
            #pragma unroll
            for (int nn = 0; nn < 8; nn++) {
                int rw = wn + nn * 8 + gr;
                bf0[nn] = Wb[sidx(rw, kb + tig)];
                bf1[nn] = Wb[sidx(rw, kb + tig + 4)];
            }
            #pragma unroll
            for (int mt = 0; mt < 2; mt++) {
                const int R  = wm + mt * 16 + gr;
                const int R8 = R + 8;
                uint32_t ah[4], al[4];
                ah[0] = Hb[sidx(R,  kb + tig)];
                ah[1] = Hb[sidx(R8, kb + tig)];
                ah[2] = Hb[sidx(R,  kb + tig + 4)];
                ah[3] = Hb[sidx(R8, kb + tig + 4)];
                al[0] = Lb[sidx(R,  kb + tig)];
                al[1] = Lb[sidx(R8, kb + tig)];
                al[2] = Lb[sidx(R,  kb + tig + 4)];
                al[3] = Lb[sidx(R8, kb + tig + 4)];
                #pragma unroll
                for (int nn = 0; nn < 8; nn++) {
                    MMA_TF32(c[mt][nn], ah, bf0[nn], bf1[nn]);
                    MMA_TF32(c[mt][nn], al, bf0[nn], bf1[nn]);
                }
            }
        }
        __syncthreads();
    }

    // Epilogue: add bias (fp32), store.
    #pragma unroll
    for (int mt = 0; mt < 2; mt++) {
        int R = m0 + wm + mt * 16 + gr;
        #pragma unroll
        for (int nn = 0; nn < 8; nn++) {
            int col = n0 + wn + nn * 8 + tig * 2;
            float2 bv = *(const float2*)(bias + col);
            float2 v0; v0.x = c[mt][nn][0] + bv.x; v0.y = c[mt][nn][1] + bv.y;
            float2 v1; v1.x = c[mt][nn][2] + bv.x; v1.y = c[mt][nn][3] + bv.y;
            *(float2*)(C + (size_t)R * N + col) = v0;
            *(float2*)(C + (size_t)(R + 8) * N + col) = v1;
        }
    }
}

// ---------------------------------------------------------------------------
// Flash attention via mma.sync m16n8k8 tf32 — 4 warps x 32 q-rows.
// (Math unchanged from Round 5/6; epilogue now writes AO as tf32 (hi,lo)
//  split — identical values the GEMM previously derived at smem-store time.)
// ---------------------------------------------------------------------------
__global__ __launch_bounds__(128, 2)
void flash_mma_kernel(const float* __restrict__ Q, const float* __restrict__ K,
                      const float* __restrict__ V,
                      uint32_t* __restrict__ AOhi, uint32_t* __restrict__ AOlo,
                      int S)
{
    __shared__ uint32_t Kt[64 * 68];
    __shared__ uint32_t Vs[64 * 68];

    const int tid  = threadIdx.x;
    const int wid  = tid >> 5;           // 0..3
    const int lane = tid & 31;
    const int gr   = lane >> 2;
    const int tig  = lane & 3;

    const int q0 = blockIdx.x * 128;
    const int b  = blockIdx.y >> 4;
    const int h  = blockIdx.y & 15;
    const int m0 = wid * 32;             // warp's q-row base within tile

    const float* Qb = Q + ((size_t)b * S + q0) * D_MODEL + h * DK;
    const float* Kb = K + (size_t)b * S * D_MODEL + h * DK;
    const float* Vb = V + (size_t)b * S * D_MODEL + h * DK;

    // Q fragments (2 m16 tiles): fold 1/sqrt(dk) * log2(e) for ex2 softmax.
    const float QSCALE = 0.125f * 1.4426950408889634f;
    uint32_t qf[8][8];
    #pragma unroll
    for (int kk = 0; kk < 8; kk++) {
        const int c0 = kk * 8 + tig;
        qf[kk][0] = f2tf32(Qb[(size_t)(m0 + gr)      * D_MODEL + c0]     * QSCALE);
        qf[kk][1] = f2tf32(Qb[(size_t)(m0 + gr + 8)  * D_MODEL + c0]     * QSCALE);
        qf[kk][2] = f2tf32(Qb[(size_t)(m0 + gr)      * D_MODEL + c0 + 4] * QSCALE);
        qf[kk][3] = f2tf32(Qb[(size_t)(m0 + gr + 8)  * D_MODEL + c0 + 4] * QSCALE);
        qf[kk][4] = f2tf32(Qb[(size_t)(m0 + gr + 16) * D_MODEL + c0]     * QSCALE);
        qf[kk][5] = f2tf32(Qb[(size_t)(m0 + gr + 24) * D_MODEL + c0]     * QSCALE);
        qf[kk][6] = f2tf32(Qb[(size_t)(m0 + gr + 16) * D_MODEL + c0 + 4] * QSCALE);
        qf[kk][7] = f2tf32(Qb[(size_t)(m0 + gr + 24) * D_MODEL + c0 + 4] * QSCALE);
    }

    float m_g[4], l_g[4];
    #pragma unroll
    for (int g = 0; g < 4; g++) { m_g[g] = -1e30f; l_g[g] = 0.0f; }
    float o[8][8];
    #pragma unroll
    for (int nn = 0; nn < 8; nn++)
        #pragma unroll
        for (int j = 0; j < 8; j++) o[nn][j] = 0.0f;

    const int srcA = (lane & 28) | (tig >> 1);  // source lane for col tig
    const int srcB = srcA + 2;                  // source lane for col tig+4
    const bool sel = (tig & 1) != 0;

    const int nkb = S >> 6;
    for (int kb = 0; kb < nkb; kb++) {
        __syncthreads();
        // Cooperative K/V tile load (64 x 64), tf32-rounded, pad-68 rows.
        #pragma unroll
        for (int i = 0; i < 8; i++) {
            int idx = tid + i * 128;
            int r = idx >> 4, c4 = idx & 15;
            float4 k4 = *(const float4*)(Kb + (size_t)(kb*64 + r) * D_MODEL + c4*4);
            uint4 ku; ku.x = f2tf32(k4.x); ku.y = f2tf32(k4.y);
                      ku.z = f2tf32(k4.z); ku.w = f2tf32(k4.w);
            *(uint4*)&Kt[r * 68 + c4 * 4] = ku;
            float4 v4 = *(const float4*)(Vb + (size_t)(kb*64 + r) * D_MODEL + c4*4);
            uint4 vu; vu.x = f2tf32(v4.x); vu.y = f2tf32(v4.y);
                      vu.z = f2tf32(v4.z); vu.w = f2tf32(v4.w);
            *(uint4*)&Vs[r * 68 + c4 * 4] = vu;
        }
        __syncthreads();

        // ---- S = Q @ K^T : warp computes 32 x 64 scores ----
        float sv[8][8];
        #pragma unroll
        for (int nn = 0; nn < 8; nn++) {
            #pragma unroll
            for (int j = 0; j < 8; j++) sv[nn][j] = 0.0f;
            #pragma unroll
            for (int kk = 0; kk < 8; kk++) {
                uint32_t b0 = Kt[(nn*8 + gr) * 68 + kk*8 + tig];
                uint32_t b1 = Kt[(nn*8 + gr) * 68 + kk*8 + tig + 4];
                MMA_TF32(&sv[nn][0], &qf[kk][0], b0, b1);   // rows m0..m0+16
                MMA_TF32(&sv[nn][4], &qf[kk][4], b0, b1);   // rows m0+16..m0+32
            }
        }

        // ---- online softmax: 4 row groups, quad-local reductions ----
        float al[4];
        #pragma unroll
        for (int g = 0; g < 4; g++) {
            float mx = -1e30f;
            #pragma unroll
            for (int nn = 0; nn < 8; nn++)
                mx = fmaxf(mx, fmaxf(sv[nn][2*g], sv[nn][2*g+1]));
            mx = fmaxf(mx, __shfl_xor_sync(0xffffffffu, mx, 1));
            mx = fmaxf(mx, __shfl_xor_sync(0xffffffffu, mx, 2));
            float mn = fmaxf(m_g[g], mx);
            al[g] = ex2f(m_g[g] - mn);
            m_g[g] = mn;
            float rs = 0.0f;
            #pragma unroll
            for (int nn = 0; nn < 8; nn++) {
                sv[nn][2*g]   = ex2f(sv[nn][2*g]   - mn);
                sv[nn][2*g+1] = ex2f(sv[nn][2*g+1] - mn);
                rs += sv[nn][2*g] + sv[nn][2*g+1];
            }
            rs += __shfl_xor_sync(0xffffffffu, rs, 1);
            rs += __shfl_xor_sync(0xffffffffu, rs, 2);
            l_g[g] = l_g[g] * al[g] + rs;
        }
        #pragma unroll
        for (int nn = 0; nn < 8; nn++)
            #pragma unroll
            for (int g = 0; g < 4; g++) {
                o[nn][2*g]   *= al[g];
                o[nn][2*g+1] *= al[g];
            }

        // ---- O += P @ V : P C-frags -> A-frags via shuffles ----
        #pragma unroll
        for (int kk = 0; kk < 8; kk++) {
            uint32_t a[8];
            #pragma unroll
            for (int t = 0; t < 2; t++) {
                float v00 = __shfl_sync(0xffffffffu, sv[kk][t*4+0], srcA);
                float v01 = __shfl_sync(0xffffffffu, sv[kk][t*4+1], srcA);
                float v10 = __shfl_sync(0xffffffffu, sv[kk][t*4+2], srcA);
                float v11 = __shfl_sync(0xffffffffu, sv[kk][t*4+3], srcA);
                float w00 = __shfl_sync(0xffffffffu, sv[kk][t*4+0], srcB);
                float w01 = __shfl_sync(0xffffffffu, sv[kk][t*4+1], srcB);
                float w10 = __shfl_sync(0xffffffffu, sv[kk][t*4+2], srcB);
                float w11 = __shfl_sync(0xffffffffu, sv[kk][t*4+3], srcB);
                a[t*4+0] = __float_as_uint(sel ? v01 : v00);
                a[t*4+1] = __float_as_uint(sel ? v11 : v10);
                a[t*4+2] = __float_as_uint(sel ? w01 : w00);
                a[t*4+3] = __float_as_uint(sel ? w11 : w10);
            }
            #pragma unroll
            for (int nn = 0; nn < 8; nn++) {
                uint32_t b0 = Vs[(kk*8 + tig)     * 68 + nn*8 + gr];
                uint32_t b1 = Vs[(kk*8 + tig + 4) * 68 + nn*8 + gr];
                MMA_TF32(&o[nn][0], &a[0], b0, b1);
                MMA_TF32(&o[nn][4], &a[4], b0, b1);
            }
        }
    }

    // ---- epilogue: normalize, write AO as tf32 (hi, lo) split ----
    float inv[4];
    #pragma unroll
    for (int g = 0; g < 4; g++) inv[g] = 1.0f / l_g[g];
    const size_t obase = ((size_t)b * S + q0) * D_MODEL + h * DK;
    const int rowg[4] = { m0 + gr, m0 + gr + 8, m0 + gr + 16, m0 + gr + 24 };
    #pragma unroll
    for (int nn = 0; nn < 8; nn++) {
        #pragma unroll
        for (int g = 0; g < 4; g++) {
            float vx = o[nn][2*g]   * inv[g];
            float vy = o[nn][2*g+1] * inv[g];
            uint2 hv, lv;
            hv.x = f2tf32(vx); lv.x = f2tf32(vx - __uint_as_float(hv.x));
            hv.y = f2tf32(vy); lv.y = f2tf32(vy - __uint_as_float(hv.y));
            size_t off = obase + (size_t)rowg[g] * D_MODEL + nn*8 + tig*2;
            *(uint2*)(AOhi + off) = hv;
            *(uint2*)(AOlo + off) = lv;
        }
    }
}

// ---------------------------------------------------------------------------
extern "C" void kernel_launch(void* const* d_in, const int* in_sizes, int n_in,
                              void* d_out, int out_size)
{
    (void)n_in; (void)out_size;
    const float* query = (const float*)d_in[0];
    const float* key   = (const float*)d_in[1];
    const float* value = (const float*)d_in[2];
    const float* Wq = (const float*)d_in[3];
    const float* bq = (const float*)d_in[4];
    const float* Wk = (const float*)d_in[5];
    const float* bk = (const float*)d_in[6];
    const float* Wv = (const float*)d_in[7];
    const float* bv = (const float*)d_in[8];
    const float* Wo = (const float*)d_in[9];
    const float* bo = (const float*)d_in[10];
    float* out = (float*)d_out;

    const int M = in_sizes[0] / D_MODEL;   // B*S = 8192
    const int S = M / BATCH;               // 4096

    float *pQ, *pK, *pV;
    uint32_t *pHi, *pLo, *pWt;
    cudaGetSymbolAddress((void**)&pQ,  g_Q);
    cudaGetSymbolAddress((void**)&pK,  g_K);
    cudaGetSymbolAddress((void**)&pV,  g_V);
    cudaGetSymbolAddress((void**)&pHi, g_hi);
    cudaGetSymbolAddress((void**)&pLo, g_lo);
    cudaGetSymbolAddress((void**)&pWt, g_Wt);

    cudaFuncSetAttribute(gemm_tf32_kernel,
                         cudaFuncAttributeMaxDynamicSharedMemorySize, GEMM_SMEM);

    const int nact = M * D_MODEL / 4 / 256;          // split grid (8192)
    const int nw   = D_MODEL * D_MODEL / 4 / 256;    // weight cvt grid (1024)
    dim3 gblk(D_MODEL / 128, M / 128);               // (8, 64)

    // Q = query @ Wq^T + bq
    split_tf32_kernel<<<nact, 256>>>(query, pHi, pLo);
    cvt_w_kernel<<<nw, 256>>>(Wq, pWt);
    gemm_tf32_kernel<<<gblk, 256, GEMM_SMEM>>>(pHi, pLo, pWt, bq, pQ, M, D_MODEL, D_MODEL);
    // K
    split_tf32_kernel<<<nact, 256>>>(key, pHi, pLo);
    cvt_w_kernel<<<nw, 256>>>(Wk, pWt);
    gemm_tf32_kernel<<<gblk, 256, GEMM_SMEM>>>(pHi, pLo, pWt, bk, pK, M, D_MODEL, D_MODEL);
    // V
    split_tf32_kernel<<<nact, 256>>>(value, pHi, pLo);
    cvt_w_kernel<<<nw, 256>>>(Wv, pWt);
    gemm_tf32_kernel<<<gblk, 256, GEMM_SMEM>>>(pHi, pLo, pWt, bv, pV, M, D_MODEL, D_MODEL);

    // Attention; writes AO directly as (hi, lo) split.
    flash_mma_kernel<<<dim3(S / 128, BATCH * N_HEADS), 128>>>(pQ, pK, pV, pHi, pLo, S);

    // out = AO @ Wo^T + bo
    cvt_w_kernel<<<nw, 256>>>(Wo, pWt);
    gemm_tf32_kernel<<<gblk, 256, GEMM_SMEM>>>(pHi, pLo, pWt, bo, out, M, D_MODEL, D_MODEL);
}